// round 1
// baseline (speedup 1.0000x reference)
#include <cuda_runtime.h>
#include <float.h>
#include <math.h>

// Problem constants (from reference setup):
//   f:         (B=4, C=64, 32, 32, 32) float32
//   inputs:    (4, 1, 128,128,128) float32  -- only shape matters; dims_max = 32
//   proposals: (N=96, 8) float32  [bidx, score, cx,cy,cz, sx,sy,sz]
//   cls_ind:   scalar (unused)
//   out:       (96, 64, 7, 7, 7) float32
//
// Box math: c0 = max(floor((c - s/2)/4), 0); c1 = min(ceil((c + s/2)/4), 32).
// L = c1-c0 is in [2, 13], so the full crop fits in a 14^3 smem tile and every
// adaptive-pool window [c0 + i*L/7, c0 + ceil((i+1)*L/7)) is non-empty and
// in-range -> exact plain max (reference's clip+mask is a no-op here).

#define RBINS 7
#define FDIM 32
#define LMAX 14

__global__ __launch_bounds__(256, 8)
void crop_roi_pool_kernel(const float* __restrict__ f,
                          const float* __restrict__ props,
                          float* __restrict__ out)
{
    const int n = blockIdx.x;   // proposal
    const int c = blockIdx.y;   // channel
    const int tid = threadIdx.x;

    // ---- box bounds (computed redundantly per thread; 8 floats, L2-hot) ----
    const float* p = props + n * 8;
    const int b = (int)p[0];

    int c0d, c0h, c0w, Ld, Lh, Lw;
    {
        float ce, si; int lo, hi;
        ce = p[2]; si = p[5];
        lo = (int)floorf((ce - si * 0.5f) * 0.25f);
        hi = (int)ceilf ((ce + si * 0.5f) * 0.25f);
        lo = max(lo, 0); hi = min(hi, FDIM);
        c0d = lo; Ld = max(hi - lo, 0);

        ce = p[3]; si = p[6];
        lo = (int)floorf((ce - si * 0.5f) * 0.25f);
        hi = (int)ceilf ((ce + si * 0.5f) * 0.25f);
        lo = max(lo, 0); hi = min(hi, FDIM);
        c0h = lo; Lh = max(hi - lo, 0);

        ce = p[4]; si = p[7];
        lo = (int)floorf((ce - si * 0.5f) * 0.25f);
        hi = (int)ceilf ((ce + si * 0.5f) * 0.25f);
        lo = max(lo, 0); hi = min(hi, FDIM);
        c0w = lo; Lw = max(hi - lo, 0);
    }

    // ---- stage the crop box into shared memory ----
    __shared__ float tile[LMAX * LMAX * LMAX];   // 14^3 * 4B = 10976 B

    const float* base = f + (((size_t)b * 64 + c) << 15)   // * 32*32*32
                          + ((c0d * FDIM + c0h) * FDIM + c0w);

    const int vol = Ld * Lh * Lw;
    for (int idx = tid; idx < vol; idx += 256) {
        const int w = idx % Lw;
        const int t = idx / Lw;
        const int h = t % Lh;
        const int d = t / Lh;
        tile[(d * LMAX + h) * LMAX + w] = base[(d * FDIM + h) * FDIM + w];
    }

    // ---- per-axis bin boundaries (relative to c0), tiny so per-thread ----
    __syncthreads();

    float* optr = out + (((size_t)n * 64 + c) * (RBINS * RBINS * RBINS));

    for (int o = tid; o < RBINS * RBINS * RBINS; o += 256) {
        const int k = o % RBINS;
        const int j = (o / RBINS) % RBINS;
        const int i = o / (RBINS * RBINS);

        const int ds = (i * Ld) / RBINS, de = ((i + 1) * Ld + RBINS - 1) / RBINS;
        const int hs = (j * Lh) / RBINS, he = ((j + 1) * Lh + RBINS - 1) / RBINS;
        const int ws = (k * Lw) / RBINS, we = ((k + 1) * Lw + RBINS - 1) / RBINS;

        float m = -FLT_MAX;
        for (int d = ds; d < de; ++d)
            for (int h = hs; h < he; ++h) {
                const float* row = &tile[(d * LMAX + h) * LMAX];
                for (int w = ws; w < we; ++w)
                    m = fmaxf(m, row[w]);
            }
        optr[o] = m;
    }
}

extern "C" void kernel_launch(void* const* d_in, const int* in_sizes, int n_in,
                              void* d_out, int out_size)
{
    const float* f     = (const float*)d_in[0];
    // d_in[1] = inputs (only used for dims_max = 32, constant here)
    const float* props = (const float*)d_in[2];
    // d_in[3] = cls_ind (unused)
    float* out = (float*)d_out;

    dim3 grid(96, 64);
    crop_roi_pool_kernel<<<grid, 256>>>(f, props, out);
}

// round 2
// speedup vs baseline: 1.5282x; 1.5282x over previous
#include <cuda_runtime.h>
#include <float.h>
#include <math.h>

// CropRoi: f (4,64,32,32,32) f32; proposals (96,8) f32; out (96,64,7,7,7) f32.
// Box: c0 = max(floor((c-s/2)/4),0), c1 = min(ceil((c+s/2)/4),32); L = c1-c0 in [2,14].
// Adaptive-max windows per axis: [i*L/7, ceil((i+1)L/7)) -- size 1..3, always in-range,
// so the reference's clip+mask == plain max over the window.
//
// Two launches (both graph-capturable):
//  1) precompute: per proposal, base offset + 343 packed window descriptors
//     (4 bits per bound) into __device__ globals. Amortized over 64 channels.
//  2) pool: no box math, no div/mod, no smem, no barriers. ~2.2 L1-hot loads/output.

#define RBINS 7
#define NBINS (RBINS * RBINS * RBINS)   // 343
#define FDIM 32
#define MAXN 1024

__device__ int g_desc[MAXN * NBINS];
__device__ int g_base[MAXN];

__global__ void precompute_kernel(const float* __restrict__ props)
{
    const int n = blockIdx.x;
    const int o = threadIdx.x;
    const float* p = props + n * 8;

    int c0[3], L[3];
#pragma unroll
    for (int ax = 0; ax < 3; ++ax) {
        const float ce = p[2 + ax], si = p[5 + ax];
        int lo = (int)floorf((ce - si * 0.5f) * 0.25f);
        int hi = (int)ceilf ((ce + si * 0.5f) * 0.25f);
        lo = max(lo, 0); hi = min(hi, FDIM);
        c0[ax] = lo;
        L[ax]  = max(hi - lo, 0);
    }

    if (o == 0) {
        const int b = (int)p[0];
        g_base[n] = ((b * 64) << 15) + ((c0[0] * FDIM + c0[1]) * FDIM + c0[2]);
    }

    if (o < NBINS) {
        const int k = o % RBINS;
        const int j = (o / RBINS) % RBINS;
        const int i = o / (RBINS * RBINS);

        const int ds = (i * L[0]) / RBINS, de = ((i + 1) * L[0] + RBINS - 1) / RBINS;
        const int hs = (j * L[1]) / RBINS, he = ((j + 1) * L[1] + RBINS - 1) / RBINS;
        const int ws = (k * L[2]) / RBINS, we = ((k + 1) * L[2] + RBINS - 1) / RBINS;

        g_desc[n * NBINS + o] =
            ds | (de << 4) | (hs << 8) | (he << 12) | (ws << 16) | (we << 20);
    }
}

__global__ __launch_bounds__(352)
void pool_kernel(const float* __restrict__ f, float* __restrict__ out)
{
    const int n = blockIdx.x;   // proposal
    const int c = blockIdx.y;   // channel
    const int o = threadIdx.x;  // output bin
    if (o >= NBINS) return;

    const int desc = g_desc[n * NBINS + o];
    const float* base = f + g_base[n] + (c << 15);

    const int ds =  desc        & 15, de = (desc >>  4) & 15;
    const int hs = (desc >>  8) & 15, he = (desc >> 12) & 15;
    const int ws = (desc >> 16) & 15, we = (desc >> 20) & 15;

    float m = -FLT_MAX;
    for (int d = ds; d < de; ++d)
        for (int h = hs; h < he; ++h) {
            const float* row = base + (d * FDIM + h) * FDIM;
            for (int w = ws; w < we; ++w)
                m = fmaxf(m, row[w]);
        }

    out[(size_t)(n * 64 + c) * NBINS + o] = m;
}

extern "C" void kernel_launch(void* const* d_in, const int* in_sizes, int n_in,
                              void* d_out, int out_size)
{
    const float* f     = (const float*)d_in[0];
    const float* props = (const float*)d_in[2];
    float* out = (float*)d_out;

    const int N = in_sizes[2] / 8;   // 96

    precompute_kernel<<<N, 352>>>(props);
    pool_kernel<<<dim3(N, 64), 352>>>(f, out);
}